// round 14
// baseline (speedup 1.0000x reference)
#include <cuda_runtime.h>
#include <cstdint>

#define BATCH 32
#define HDIM 512
#define WDIM 512
#define NPIX (HDIM * WDIM)
#define KTOP 1000
#define KPRIME 1280
#define NTILES 128          // 8 x 16 tiles of 64x32
#define MAXTILE 512
#define TPC 16              // tiles per prepare-CTA
#define NSEL 2048
#define STAGE_CAP 1536
#define HBINS 2048
#define DELTA 2e-4f

#define TILE_W 64
#define TILE_H 32
#define HALO_W 66
#define HALO_H 34
#define APITCH 68

// -------- static device scratch (zero-initialized at module load) --------
__device__ unsigned long long g_tile[BATCH][NTILES][MAXTILE];
__device__ int g_tcnt[BATCH][NTILES];
__device__ unsigned int g_hist[BATCH][HBINS];        // re-zeroed by sort_emit
__device__ unsigned long long g_sel[BATCH][NSEL];
__device__ int g_nsel[BATCH];                        // re-zeroed by sort_emit

// -------- XLA:CPU GenerateVF32Exp (Cephes, non-FMA) — bit-exact reference --------
__device__ __forceinline__ float xla_cpu_expf(float x) {
    const float exp_hi = 88.3762626647950f;
    const float exp_lo = -88.3762626647949f;
    const float log2ef = 1.44269504088896341f;
    const float c1 = 0.693359375f;
    const float c2 = -2.12194440e-4f;

    float xc = fminf(fmaxf(x, exp_lo), exp_hi);
    float fx = floorf(__fadd_rn(__fmul_rn(xc, log2ef), 0.5f));
    float tmp = __fmul_rn(c1, fx);
    float z = __fmul_rn(c2, fx);
    float r = __fsub_rn(xc, tmp);
    r = __fsub_rn(r, z);
    z = __fmul_rn(r, r);

    float y = 1.9875691500E-4f;
    y = __fadd_rn(__fmul_rn(y, r), 1.3981999507E-3f);
    y = __fadd_rn(__fmul_rn(y, r), 8.3334519073E-3f);
    y = __fadd_rn(__fmul_rn(y, r), 4.1665795894E-2f);
    y = __fadd_rn(__fmul_rn(y, r), 1.6666665459E-1f);
    y = __fadd_rn(__fmul_rn(y, r), 5.0000001201E-1f);
    y = __fadd_rn(__fmul_rn(y, z), r);
    y = __fadd_rn(y, 1.0f);

    int emm0 = (((int)fx) + 0x7f) << 23;
    return __fmul_rn(y, __int_as_float(emm0));
}

__device__ __forceinline__ float xla_sigmoidf(float x) {
    float e = xla_cpu_expf(-x);
    return __fdiv_rn(1.0f, __fadd_rn(1.0f, e));
}

__device__ __forceinline__ float score_fn(float r, float u) {
    float s  = xla_sigmoidf(r);
    float p  = __fmul_rn(s, s);
    float su = xla_sigmoidf(u);
    float m  = __fsub_rn(1.0f, __fmul_rn(0.35f, su));
    return __fmul_rn(p, m);
}

// cheap approximate score; |approx - exact| <= ~1e-5 << DELTA
__device__ __forceinline__ float approx_score(float r, float u) {
    float s = __fdividef(1.0f, 1.0f + __expf(-r));
    float m = 1.0f - 0.35f * __fdividef(1.0f, 1.0f + __expf(-u));
    return s * s * m;
}

// monotone bin: exponents 119..126 (scores in [2^-8,1)), 8 mantissa bits.
__device__ __forceinline__ unsigned binkey_of(unsigned sb) {
    return (sb < 0x3B800000u) ? 0u : (((sb >> 15) & 0xFFFu) - 1792u);
}

// warp-wide inclusive suffix sum (lane l gets sum over lanes >= l)
__device__ __forceinline__ unsigned warp_suffix(unsigned x, int lane) {
    #pragma unroll
    for (int off = 1; off < 32; off <<= 1) {
        unsigned v = __shfl_down_sync(0xFFFFFFFFu, x, off);
        if (lane + off < 32) x += v;
    }
    return x;
}

__device__ __forceinline__ unsigned long long ullmin2(unsigned long long a, unsigned long long b) {
    return a < b ? a : b;
}
__device__ __forceinline__ unsigned long long ullmax2(unsigned long long a, unsigned long long b) {
    return a > b ? a : b;
}

// -------- kernel 1: approx score + separable-max margin NMS (64x32 tiles) --------
__global__ __launch_bounds__(256) void peaks_kernel(const float* __restrict__ route,
                                                    const float* __restrict__ unc) {
    __shared__ float ap[HALO_H * APITCH];
    __shared__ unsigned int sh_hist[HBINS];
    __shared__ unsigned long long sbuf[MAXTILE];
    __shared__ int scnt;

    int b = blockIdx.z;
    int tileId = blockIdx.y * 8 + blockIdx.x;
    int tx0 = blockIdx.x * TILE_W;
    int ty0 = blockIdx.y * TILE_H;
    const float* rp = route + (size_t)b * NPIX;
    const float* up = unc + (size_t)b * NPIX;
    int tid = threadIdx.x;

    if (tid == 0) scnt = 0;
    #pragma unroll
    for (int j = 0; j < HBINS / 256; j++) sh_hist[tid + j * 256] = 0u;

    // stage approx scores for the 66x34 halo region
    for (int i = tid; i < HALO_W * HALO_H; i += 256) {
        int r = i / HALO_W;
        int c = i - r * HALO_W;
        int gx = tx0 - 1 + c;
        int gy = ty0 - 1 + r;
        float a = -1e30f;
        if ((unsigned)gx < (unsigned)WDIM && (unsigned)gy < (unsigned)HDIM) {
            int idx = (gy << 9) | gx;
            a = approx_score(rp[idx], up[idx]);
        }
        ap[r * APITCH + c] = a;
    }
    __syncthreads();

    // NMS: each thread handles a 1x4 strip; 2 passes cover 32 rows.
    #pragma unroll
    for (int p = 0; p < 2; p++) {
        int row = p * 16 + (tid >> 4);        // tile-local row 0..31
        int c0 = (tid & 15) << 2;             // tile-local col of strip start
        int base = (row + 1) * APITCH + c0;   // ap index of column c0, center row

        float vm2[6], h3[6], mid[6];
        #pragma unroll
        for (int j = 0; j < 6; j++) {
            float t  = ap[base - APITCH + j];
            float m  = ap[base + j];
            float bo = ap[base + APITCH + j];
            vm2[j] = fmaxf(t, bo);
            h3[j]  = fmaxf(vm2[j], m);
            mid[j] = m;
        }
        #pragma unroll
        for (int jj = 0; jj < 4; jj++) {
            float a = mid[jj + 1];
            float nmax = fmaxf(fmaxf(h3[jj], h3[jj + 2]), vm2[jj + 1]);
            float d = a - nmax;
            if (d >= -DELTA) {                 // not a definite loss
                bool amb = (d <= DELTA);
                unsigned idx = (unsigned)(((ty0 + row) << 9) | (tx0 + c0 + jj));
                unsigned sb = __float_as_uint(a);
                unsigned lo = idx | (amb ? 0x80000000u : 0u);
                unsigned long long key =
                    ((unsigned long long)sb << 32) | (unsigned long long)lo;
                int pp = atomicAdd(&scnt, 1);
                if (pp < MAXTILE) {
                    sbuf[pp] = key;
                    atomicAdd(&sh_hist[binkey_of(sb)], 1u);
                }
            }
        }
    }
    __syncthreads();

    int nc = scnt; if (nc > MAXTILE) nc = MAXTILE;
    if (tid == 0) g_tcnt[b][tileId] = nc;
    for (int i = tid; i < nc; i += 256) g_tile[b][tileId][i] = sbuf[i];
    #pragma unroll
    for (int j = 0; j < HBINS / 256; j++) {
        int i = tid + j * 256;
        unsigned c = sh_hist[i];
        if (c) atomicAdd(&g_hist[b][i], c);
    }
}

// -------- kernel 2: per-batch threshold + compact + exact rescore (256 CTAs) --------
__global__ __launch_bounds__(256) void prepare_kernel(const float* __restrict__ route,
                                                      const float* __restrict__ unc) {
    __shared__ unsigned long long sbuf[STAGE_CAP];
    __shared__ unsigned int wtot[8];
    __shared__ unsigned int wsuf[32];
    __shared__ int sB;
    __shared__ int s_stage;

    int b = blockIdx.y;
    int t0 = blockIdx.x * TPC;
    int tid = threadIdx.x;
    int wid = tid >> 5, lane = tid & 31;

    if (tid == 0) { sB = 0; s_stage = 0; }
    __syncthreads();

    // ---- threshold scan: thread owns bins [8*tid, 8*tid+8) of g_hist[b] ----
    unsigned hb[8];
    unsigned tsum = 0;
    #pragma unroll
    for (int j = 0; j < 8; j++) { hb[j] = g_hist[b][tid * 8 + j]; tsum += hb[j]; }
    unsigned x = warp_suffix(tsum, lane);
    if (lane == 0) wtot[wid] = x;
    __syncthreads();
    if (wid == 0) {
        unsigned w = (lane < 8) ? wtot[lane] : 0u;
        unsigned y = warp_suffix(w, lane);
        wsuf[lane] = y;
    }
    __syncthreads();
    {
        unsigned later = (wid + 1 < 8) ? wsuf[wid + 1] : 0u;
        unsigned inc = x + later;
        unsigned above = inc - tsum;
        if (above < (unsigned)KPRIME && inc >= (unsigned)KPRIME) {
            unsigned acc = above;
            for (int j = 7; j >= 0; --j) {
                if (acc + hb[j] >= (unsigned)KPRIME) { sB = tid * 8 + j; break; }
                acc += hb[j];
            }
        }
    }
    __syncthreads();
    int B = sB;

    // ---- compact this CTA's TPC tiles: keys with bin >= B -> smem stage ----
    for (int t = t0 + wid; t < t0 + TPC; t += 8) {
        int n = g_tcnt[b][t];
        int nr = (n + 31) & ~31;
        for (int i = lane; i < nr; i += 32) {
            bool valid = (i < n);
            unsigned long long key = valid ? g_tile[b][t][i] : 0ull;
            bool take = valid &&
                        (binkey_of((unsigned)(key >> 32)) >= (unsigned)B);
            unsigned m = __ballot_sync(0xFFFFFFFFu, take);
            if (take) {
                int leader = __ffs(m) - 1;
                int rank = __popc(m & ((1u << lane) - 1u));
                int base = 0;
                if (lane == leader) base = atomicAdd(&s_stage, __popc(m));
                base = __shfl_sync(m, base, leader);
                int p = base + rank;
                if (p < STAGE_CAP) sbuf[p] = key;
            }
        }
    }
    __syncthreads();

    // ---- exact rescore of staged keys; survivors -> g_sel[b] ----
    const float* rp = route + (size_t)b * NPIX;
    const float* up = unc + (size_t)b * NPIX;
    const int DY[8] = {-1,-1,-1, 0, 0, 1, 1, 1};
    const int DX[8] = {-1, 0, 1,-1, 1,-1, 0, 1};

    int m = s_stage; if (m > STAGE_CAP) m = STAGE_CAP;
    int mr = (m + 255) & ~255;
    for (int i = tid; i < mr; i += 256) {
        bool valid = (i < m);
        unsigned long long nk = 0ull;
        bool ok = false;
        if (valid) {
            unsigned lo = (unsigned)sbuf[i];
            unsigned idx = lo & 0x3FFFFu;
            bool amb = (lo >> 31) != 0u;
            float v = score_fn(rp[idx], up[idx]);
            ok = true;
            if (amb) {
                int y = (int)(idx >> 9), x2i = (int)(idx & 511);
                #pragma unroll
                for (int j = 0; j < 8; j++) {
                    int nx = x2i + DX[j], ny = y + DY[j];
                    if (nx >= 0 && nx < WDIM && ny >= 0 && ny < HDIM) {
                        int nidx = (ny << 9) | nx;
                        float vn = score_fn(rp[nidx], up[nidx]);
                        if (!(v >= vn)) { ok = false; break; }
                    }
                }
            }
            if (ok) {
                nk = ((unsigned long long)__float_as_uint(v) << 32) |
                     (unsigned long long)(~idx);
            }
        }
        unsigned bm = __ballot_sync(0xFFFFFFFFu, ok);
        if (ok) {
            int leader = __ffs(bm) - 1;
            int rank = __popc(bm & ((1u << lane) - 1u));
            int base = 0;
            if (lane == leader) base = atomicAdd(&g_nsel[b], __popc(bm));
            base = __shfl_sync(bm, base, leader);
            int p = base + rank;
            if (p < NSEL) g_sel[b][p] = nk;
        }
    }
}

// -------- kernel 3: sort exact keys + emit (32 CTAs) --------
__global__ __launch_bounds__(1024) void sort_emit_kernel(const float* __restrict__ unc,
                                                         const float* __restrict__ scale,
                                                         const int* __restrict__ p_ih,
                                                         const int* __restrict__ p_iw,
                                                         float* __restrict__ out) {
    __shared__ unsigned long long skeys[NSEL];

    int b = blockIdx.x;
    int tid = threadIdx.x;

    int n = g_nsel[b]; if (n > NSEL) n = NSEL;
    skeys[tid]        = (tid < n)        ? g_sel[b][tid]        : 0ull;
    skeys[tid + 1024] = (tid + 1024 < n) ? g_sel[b][tid + 1024] : 0ull;
    __syncthreads();

    // register/shfl bitonic sort of 2048 (ascending; zeros sort to front)
    {
        unsigned long long v0 = skeys[tid];
        unsigned long long v1 = skeys[tid + 1024];
        const int i0 = tid, i1 = tid + 1024;

        for (int size = 2; size <= 2048; size <<= 1) {
            for (int stride = size >> 1; stride > 0; stride >>= 1) {
                if (stride == 1024) {
                    bool up0 = ((i0 & size) == 0);
                    if ((v0 > v1) == up0) { unsigned long long t = v0; v0 = v1; v1 = t; }
                } else if (stride >= 32) {
                    __syncthreads();
                    skeys[i0] = v0; skeys[i1] = v1;
                    __syncthreads();
                    unsigned long long p0 = skeys[i0 ^ stride];
                    unsigned long long p1 = skeys[i1 ^ stride];
                    bool up0 = ((i0 & size) == 0), le0 = ((i0 & stride) == 0);
                    bool up1 = ((i1 & size) == 0), le1 = ((i1 & stride) == 0);
                    v0 = (le0 == up0) ? ullmin2(v0, p0) : ullmax2(v0, p0);
                    v1 = (le1 == up1) ? ullmin2(v1, p1) : ullmax2(v1, p1);
                } else {
                    unsigned long long p0 = __shfl_xor_sync(0xFFFFFFFFu, v0, stride);
                    unsigned long long p1 = __shfl_xor_sync(0xFFFFFFFFu, v1, stride);
                    bool up0 = ((i0 & size) == 0), le0 = ((i0 & stride) == 0);
                    bool up1 = ((i1 & size) == 0), le1 = ((i1 & stride) == 0);
                    v0 = (le0 == up0) ? ullmin2(v0, p0) : ullmax2(v0, p0);
                    v1 = (le1 == up1) ? ullmin2(v1, p1) : ullmax2(v1, p1);
                }
            }
        }
        __syncthreads();
        skeys[i0] = v0; skeys[i1] = v1;
        __syncthreads();
    }

    int k = n; if (k > KTOP) k = KTOP;
    const float* up = unc + (size_t)b * NPIX;

    if (tid < KTOP) {
        float iw = (float)p_iw[0];
        float ih = (float)p_ih[0];
        float bcol = 0.f, x1 = 0.f, y1 = 0.f, x2 = 0.f, y2 = 0.f, scv = 0.f, vv = 0.f;
        if (tid < k) {
            unsigned long long key = skeys[2047 - tid];
            float v = __uint_as_float((unsigned)(key >> 32));
            unsigned idx = (~((unsigned)key)) & 0x3FFFFu;
            int y = (int)(idx >> 9);
            int x = (int)(idx & 511);
            float cx = __fmul_rn(__fadd_rn((float)x, 0.5f), 4.0f);
            float cy = __fmul_rn(__fadd_rn((float)y, 0.5f), 4.0f);
            float sc = scale[(size_t)b * NPIX + idx];
            float un = xla_sigmoidf(up[idx]);
            float side = __fadd_rn(32.0f, __fmul_rn(xla_sigmoidf(sc), 480.0f));
            side = __fmul_rn(side, __fadd_rn(1.0f, __fmul_rn(0.25f, un)));
            float half = __fmul_rn(side, 0.5f);
            x1 = fminf(fmaxf(__fsub_rn(cx, half), 0.0f), __fsub_rn(iw, 1.0f));
            y1 = fminf(fmaxf(__fsub_rn(cy, half), 0.0f), __fsub_rn(ih, 1.0f));
            x2 = fminf(fmaxf(__fadd_rn(cx, half), 1.0f), iw);
            y2 = fminf(fmaxf(__fadd_rn(cy, half), 1.0f), ih);
            bcol = (float)b;
            scv = v;
            vv = 1.0f;
        }
        int t = b * KTOP + tid;
        float* roi = out + (size_t)t * 5;
        roi[0] = bcol; roi[1] = x1; roi[2] = y1; roi[3] = x2; roi[4] = y2;
        out[(size_t)BATCH * KTOP * 5 + t] = scv;
        out[(size_t)BATCH * KTOP * 6 + t] = vv;
    }

    // cleanup for next graph replay (deterministic state)
    for (int i = tid; i < HBINS; i += 1024) g_hist[b][i] = 0u;
    if (tid == 0) g_nsel[b] = 0;
}

extern "C" void kernel_launch(void* const* d_in, const int* in_sizes, int n_in,
                              void* d_out, int out_size) {
    const float* route = (const float*)d_in[0];
    const float* scale = (const float*)d_in[1];
    const float* uncl  = (const float*)d_in[2];
    const int*   p_ih  = (const int*)d_in[3];
    const int*   p_iw  = (const int*)d_in[4];
    float* out = (float*)d_out;

    dim3 grid1(WDIM / TILE_W, HDIM / TILE_H, BATCH);
    peaks_kernel<<<grid1, 256>>>(route, uncl);

    dim3 grid2(NTILES / TPC, BATCH);
    prepare_kernel<<<grid2, 256>>>(route, uncl);

    sort_emit_kernel<<<BATCH, 1024>>>(uncl, scale, p_ih, p_iw, out);
}

// round 15
// speedup vs baseline: 1.3213x; 1.3213x over previous
#include <cuda_runtime.h>
#include <cstdint>

#define BATCH 32
#define HDIM 512
#define WDIM 512
#define NPIX (HDIM * WDIM)
#define KTOP 1000
#define KPRIME 1280
#define NTILES 256          // 16 x 16 tiles of 32x32
#define MAXTILE 256
#define TPC 16              // tiles per prepare-CTA
#define NSEL 2048
#define STAGE_CAP 1536
#define HBINS 512
#define DELTA 2e-4f
#define APITCH 36

// -------- static device scratch (zero-initialized at module load) --------
__device__ unsigned long long g_tile[BATCH][NTILES][MAXTILE];
__device__ int g_tcnt[BATCH][NTILES];
__device__ unsigned int g_hist[BATCH][HBINS];        // re-zeroed by sort_emit
__device__ unsigned long long g_sel[BATCH][NSEL];
__device__ int g_nsel[BATCH];                        // re-zeroed by sort_emit

// -------- XLA:CPU GenerateVF32Exp (Cephes, non-FMA) — bit-exact reference --------
__device__ __forceinline__ float xla_cpu_expf(float x) {
    const float exp_hi = 88.3762626647950f;
    const float exp_lo = -88.3762626647949f;
    const float log2ef = 1.44269504088896341f;
    const float c1 = 0.693359375f;
    const float c2 = -2.12194440e-4f;

    float xc = fminf(fmaxf(x, exp_lo), exp_hi);
    float fx = floorf(__fadd_rn(__fmul_rn(xc, log2ef), 0.5f));
    float tmp = __fmul_rn(c1, fx);
    float z = __fmul_rn(c2, fx);
    float r = __fsub_rn(xc, tmp);
    r = __fsub_rn(r, z);
    z = __fmul_rn(r, r);

    float y = 1.9875691500E-4f;
    y = __fadd_rn(__fmul_rn(y, r), 1.3981999507E-3f);
    y = __fadd_rn(__fmul_rn(y, r), 8.3334519073E-3f);
    y = __fadd_rn(__fmul_rn(y, r), 4.1665795894E-2f);
    y = __fadd_rn(__fmul_rn(y, r), 1.6666665459E-1f);
    y = __fadd_rn(__fmul_rn(y, r), 5.0000001201E-1f);
    y = __fadd_rn(__fmul_rn(y, z), r);
    y = __fadd_rn(y, 1.0f);

    int emm0 = (((int)fx) + 0x7f) << 23;
    return __fmul_rn(y, __int_as_float(emm0));
}

__device__ __forceinline__ float xla_sigmoidf(float x) {
    float e = xla_cpu_expf(-x);
    return __fdiv_rn(1.0f, __fadd_rn(1.0f, e));
}

__device__ __forceinline__ float score_fn(float r, float u) {
    float s  = xla_sigmoidf(r);
    float p  = __fmul_rn(s, s);
    float su = xla_sigmoidf(u);
    float m  = __fsub_rn(1.0f, __fmul_rn(0.35f, su));
    return __fmul_rn(p, m);
}

// cheap approximate score via single reciprocal:
// s^2 * (1 - 0.35*su) == (0.65 + e_u) / ((1+e_r)^2 (1+e_u));  |err| <= ~1e-5 << DELTA
__device__ __forceinline__ float approx_score(float r, float u) {
    float er = __expf(-r);
    float eu = __expf(-u);
    float d1 = 1.0f + er;
    float den = d1 * d1 * (1.0f + eu);
    return __fdividef(0.65f + eu, den);
}

// 9-bit monotone bin: exponents 119..126 (scores in [2^-8,1)), 6 mantissa bits.
__device__ __forceinline__ unsigned binkey_of(unsigned sb) {
    return (sb < 0x3B800000u) ? 0u : (((sb >> 17) & 0x3FFu) - 448u);
}

// warp-wide inclusive suffix sum (lane l gets sum over lanes >= l)
__device__ __forceinline__ unsigned warp_suffix(unsigned x, int lane) {
    #pragma unroll
    for (int off = 1; off < 32; off <<= 1) {
        unsigned v = __shfl_down_sync(0xFFFFFFFFu, x, off);
        if (lane + off < 32) x += v;
    }
    return x;
}

__device__ __forceinline__ unsigned long long ullmin2(unsigned long long a, unsigned long long b) {
    return a < b ? a : b;
}
__device__ __forceinline__ unsigned long long ullmax2(unsigned long long a, unsigned long long b) {
    return a > b ? a : b;
}

// -------- kernel 1: approx score + separable-max margin NMS (32x32 tiles) --------
__global__ __launch_bounds__(256) void peaks_kernel(const float* __restrict__ route,
                                                    const float* __restrict__ unc) {
    __shared__ float ap[34 * APITCH];
    __shared__ unsigned int sh_hist[HBINS];
    __shared__ unsigned long long sbuf[MAXTILE];
    __shared__ int scnt;

    int b = blockIdx.z;
    int tileId = blockIdx.y * 16 + blockIdx.x;
    int tx0 = blockIdx.x * 32;
    int ty0 = blockIdx.y * 32;
    const float* rp = route + (size_t)b * NPIX;
    const float* up = unc + (size_t)b * NPIX;
    int tid = threadIdx.x;
    int lane = tid & 31;

    if (tid == 0) scnt = 0;
    sh_hist[tid] = 0u;
    if (tid < HBINS - 256) sh_hist[tid + 256] = 0u;

    // stage approx scores for the 34x34 halo (div-free addressing)
    {
        int col = lane;            // 0..31
        int rg = tid >> 5;         // 0..7
        for (int r = rg; r < 34; r += 8) {
            int gy = ty0 - 1 + r;
            bool rowok = ((unsigned)gy < (unsigned)HDIM);
            int rowbase = r * APITCH;
            // column col (0..31)
            {
                int gx = tx0 - 1 + col;
                float a = -1e30f;
                if (rowok && (unsigned)gx < (unsigned)WDIM) {
                    int idx = (gy << 9) | gx;
                    a = approx_score(rp[idx], up[idx]);
                }
                ap[rowbase + col] = a;
            }
            // columns 32,33 handled by lanes 0,1
            if (col < 2) {
                int c = col + 32;
                int gx = tx0 - 1 + c;
                float a = -1e30f;
                if (rowok && (unsigned)gx < (unsigned)WDIM) {
                    int idx = (gy << 9) | gx;
                    a = approx_score(rp[idx], up[idx]);
                }
                ap[rowbase + c] = a;
            }
        }
    }
    __syncthreads();

    // NMS: each thread handles a 1x4 strip (one pass covers the 32x32 tile)
    {
        int row = tid >> 3;               // 0..31
        int c0 = (tid & 7) << 2;          // 0,4,...,28
        int base = (row + 1) * APITCH + c0;  // halo coords of (row, c0-1)

        float vm2[6], h3[6], mid[6];
        #pragma unroll
        for (int j = 0; j < 6; j++) {
            float t  = ap[base - APITCH + j];
            float m  = ap[base + j];
            float bo = ap[base + APITCH + j];
            vm2[j] = fmaxf(t, bo);
            h3[j]  = fmaxf(vm2[j], m);
            mid[j] = m;
        }
        #pragma unroll
        for (int jj = 0; jj < 4; jj++) {
            float a = mid[jj + 1];
            float nmax = fmaxf(fmaxf(h3[jj], h3[jj + 2]), vm2[jj + 1]);
            float d = a - nmax;
            if (d >= -DELTA) {                 // not a definite loss
                bool amb = (d <= DELTA);
                unsigned idx = (unsigned)(((ty0 + row) << 9) | (tx0 + c0 + jj));
                unsigned sb = __float_as_uint(a);
                unsigned lo = idx | (amb ? 0x80000000u : 0u);
                unsigned long long key =
                    ((unsigned long long)sb << 32) | (unsigned long long)lo;
                int pp = atomicAdd(&scnt, 1);
                if (pp < MAXTILE) {
                    sbuf[pp] = key;
                    atomicAdd(&sh_hist[binkey_of(sb)], 1u);
                }
            }
        }
    }
    __syncthreads();

    int nc = scnt; if (nc > MAXTILE) nc = MAXTILE;
    if (tid == 0) g_tcnt[b][tileId] = nc;
    if (tid < nc) g_tile[b][tileId][tid] = sbuf[tid];
    {
        unsigned c = sh_hist[tid];
        if (c) atomicAdd(&g_hist[b][tid], c);
        if (tid < HBINS - 256) {
            unsigned c2 = sh_hist[tid + 256];
            if (c2) atomicAdd(&g_hist[b][tid + 256], c2);
        }
    }
}

// -------- kernel 2: per-batch threshold + compact + exact rescore (512 CTAs) --------
__global__ __launch_bounds__(256) void prepare_kernel(const float* __restrict__ route,
                                                      const float* __restrict__ unc) {
    __shared__ unsigned long long sbuf[STAGE_CAP];
    __shared__ unsigned int wtot[8];
    __shared__ unsigned int wsuf[32];
    __shared__ int sB;
    __shared__ int s_stage;

    int b = blockIdx.y;
    int t0 = blockIdx.x * TPC;
    int tid = threadIdx.x;
    int wid = tid >> 5, lane = tid & 31;

    if (tid == 0) { sB = 0; s_stage = 0; }
    __syncthreads();

    // ---- threshold scan: thread owns bins [2*tid, 2*tid+2) of g_hist[b] ----
    unsigned hb0 = g_hist[b][tid * 2];
    unsigned hb1 = g_hist[b][tid * 2 + 1];
    unsigned tsum = hb0 + hb1;
    unsigned x = warp_suffix(tsum, lane);
    if (lane == 0) wtot[wid] = x;
    __syncthreads();
    if (wid == 0) {
        unsigned w = (lane < 8) ? wtot[lane] : 0u;
        unsigned y = warp_suffix(w, lane);
        wsuf[lane] = y;
    }
    __syncthreads();
    {
        unsigned later = (wid + 1 < 8) ? wsuf[wid + 1] : 0u;
        unsigned inc = x + later;                 // count over bins >= 2*tid
        unsigned above = inc - tsum;              // count over bins >= 2*tid+2
        if (above < (unsigned)KPRIME && inc >= (unsigned)KPRIME) {
            if (above + hb1 >= (unsigned)KPRIME) sB = tid * 2 + 1;
            else sB = tid * 2;
        }
    }
    __syncthreads();
    int B = sB;

    // ---- compact this CTA's TPC tiles: keys with bin >= B -> smem stage ----
    for (int t = t0 + wid; t < t0 + TPC; t += 8) {
        int n = g_tcnt[b][t];
        int nr = (n + 31) & ~31;
        for (int i = lane; i < nr; i += 32) {
            bool valid = (i < n);
            unsigned long long key = valid ? g_tile[b][t][i] : 0ull;
            bool take = valid &&
                        (binkey_of((unsigned)(key >> 32)) >= (unsigned)B);
            unsigned m = __ballot_sync(0xFFFFFFFFu, take);
            if (take) {
                int leader = __ffs(m) - 1;
                int rank = __popc(m & ((1u << lane) - 1u));
                int base = 0;
                if (lane == leader) base = atomicAdd(&s_stage, __popc(m));
                base = __shfl_sync(m, base, leader);
                int p = base + rank;
                if (p < STAGE_CAP) sbuf[p] = key;
            }
        }
    }
    __syncthreads();

    // ---- exact rescore of staged keys; survivors -> g_sel[b] ----
    const float* rp = route + (size_t)b * NPIX;
    const float* up = unc + (size_t)b * NPIX;
    const int DY[8] = {-1,-1,-1, 0, 0, 1, 1, 1};
    const int DX[8] = {-1, 0, 1,-1, 1,-1, 0, 1};

    int m = s_stage; if (m > STAGE_CAP) m = STAGE_CAP;
    int mr = (m + 255) & ~255;
    for (int i = tid; i < mr; i += 256) {
        bool valid = (i < m);
        unsigned long long nk = 0ull;
        bool ok = false;
        if (valid) {
            unsigned lo = (unsigned)sbuf[i];
            unsigned idx = lo & 0x3FFFFu;
            bool amb = (lo >> 31) != 0u;
            float v = score_fn(rp[idx], up[idx]);
            ok = true;
            if (amb) {
                int y = (int)(idx >> 9), x2i = (int)(idx & 511);
                #pragma unroll
                for (int j = 0; j < 8; j++) {
                    int nx = x2i + DX[j], ny = y + DY[j];
                    if (nx >= 0 && nx < WDIM && ny >= 0 && ny < HDIM) {
                        int nidx = (ny << 9) | nx;
                        float vn = score_fn(rp[nidx], up[nidx]);
                        if (!(v >= vn)) { ok = false; break; }
                    }
                }
            }
            if (ok) {
                nk = ((unsigned long long)__float_as_uint(v) << 32) |
                     (unsigned long long)(~idx);
            }
        }
        unsigned bm = __ballot_sync(0xFFFFFFFFu, ok);
        if (ok) {
            int leader = __ffs(bm) - 1;
            int rank = __popc(bm & ((1u << lane) - 1u));
            int base = 0;
            if (lane == leader) base = atomicAdd(&g_nsel[b], __popc(bm));
            base = __shfl_sync(bm, base, leader);
            int p = base + rank;
            if (p < NSEL) g_sel[b][p] = nk;
        }
    }
}

// -------- kernel 3: sort exact keys + emit (32 CTAs) --------
__global__ __launch_bounds__(1024) void sort_emit_kernel(const float* __restrict__ unc,
                                                         const float* __restrict__ scale,
                                                         const int* __restrict__ p_ih,
                                                         const int* __restrict__ p_iw,
                                                         float* __restrict__ out) {
    __shared__ unsigned long long skeys[NSEL];

    int b = blockIdx.x;
    int tid = threadIdx.x;

    int n = g_nsel[b]; if (n > NSEL) n = NSEL;
    skeys[tid]        = (tid < n)        ? g_sel[b][tid]        : 0ull;
    skeys[tid + 1024] = (tid + 1024 < n) ? g_sel[b][tid + 1024] : 0ull;
    __syncthreads();

    // register/shfl bitonic sort of 2048 (ascending; zeros sort to front)
    {
        unsigned long long v0 = skeys[tid];
        unsigned long long v1 = skeys[tid + 1024];
        const int i0 = tid, i1 = tid + 1024;

        for (int size = 2; size <= 2048; size <<= 1) {
            for (int stride = size >> 1; stride > 0; stride >>= 1) {
                if (stride == 1024) {
                    bool up0 = ((i0 & size) == 0);
                    if ((v0 > v1) == up0) { unsigned long long t = v0; v0 = v1; v1 = t; }
                } else if (stride >= 32) {
                    __syncthreads();
                    skeys[i0] = v0; skeys[i1] = v1;
                    __syncthreads();
                    unsigned long long p0 = skeys[i0 ^ stride];
                    unsigned long long p1 = skeys[i1 ^ stride];
                    bool up0 = ((i0 & size) == 0), le0 = ((i0 & stride) == 0);
                    bool up1 = ((i1 & size) == 0), le1 = ((i1 & stride) == 0);
                    v0 = (le0 == up0) ? ullmin2(v0, p0) : ullmax2(v0, p0);
                    v1 = (le1 == up1) ? ullmin2(v1, p1) : ullmax2(v1, p1);
                } else {
                    unsigned long long p0 = __shfl_xor_sync(0xFFFFFFFFu, v0, stride);
                    unsigned long long p1 = __shfl_xor_sync(0xFFFFFFFFu, v1, stride);
                    bool up0 = ((i0 & size) == 0), le0 = ((i0 & stride) == 0);
                    bool up1 = ((i1 & size) == 0), le1 = ((i1 & stride) == 0);
                    v0 = (le0 == up0) ? ullmin2(v0, p0) : ullmax2(v0, p0);
                    v1 = (le1 == up1) ? ullmin2(v1, p1) : ullmax2(v1, p1);
                }
            }
        }
        __syncthreads();
        skeys[i0] = v0; skeys[i1] = v1;
        __syncthreads();
    }

    int k = n; if (k > KTOP) k = KTOP;
    const float* up = unc + (size_t)b * NPIX;

    if (tid < KTOP) {
        float iw = (float)p_iw[0];
        float ih = (float)p_ih[0];
        float bcol = 0.f, x1 = 0.f, y1 = 0.f, x2 = 0.f, y2 = 0.f, scv = 0.f, vv = 0.f;
        if (tid < k) {
            unsigned long long key = skeys[2047 - tid];
            float v = __uint_as_float((unsigned)(key >> 32));
            unsigned idx = (~((unsigned)key)) & 0x3FFFFu;
            int y = (int)(idx >> 9);
            int x = (int)(idx & 511);
            float cx = __fmul_rn(__fadd_rn((float)x, 0.5f), 4.0f);
            float cy = __fmul_rn(__fadd_rn((float)y, 0.5f), 4.0f);
            float sc = scale[(size_t)b * NPIX + idx];
            float un = xla_sigmoidf(up[idx]);
            float side = __fadd_rn(32.0f, __fmul_rn(xla_sigmoidf(sc), 480.0f));
            side = __fmul_rn(side, __fadd_rn(1.0f, __fmul_rn(0.25f, un)));
            float half = __fmul_rn(side, 0.5f);
            x1 = fminf(fmaxf(__fsub_rn(cx, half), 0.0f), __fsub_rn(iw, 1.0f));
            y1 = fminf(fmaxf(__fsub_rn(cy, half), 0.0f), __fsub_rn(ih, 1.0f));
            x2 = fminf(fmaxf(__fadd_rn(cx, half), 1.0f), iw);
            y2 = fminf(fmaxf(__fadd_rn(cy, half), 1.0f), ih);
            bcol = (float)b;
            scv = v;
            vv = 1.0f;
        }
        int t = b * KTOP + tid;
        float* roi = out + (size_t)t * 5;
        roi[0] = bcol; roi[1] = x1; roi[2] = y1; roi[3] = x2; roi[4] = y2;
        out[(size_t)BATCH * KTOP * 5 + t] = scv;
        out[(size_t)BATCH * KTOP * 6 + t] = vv;
    }

    // cleanup for next graph replay (deterministic state)
    if (tid < HBINS) g_hist[b][tid] = 0u;
    if (tid == 0) g_nsel[b] = 0;
}

extern "C" void kernel_launch(void* const* d_in, const int* in_sizes, int n_in,
                              void* d_out, int out_size) {
    const float* route = (const float*)d_in[0];
    const float* scale = (const float*)d_in[1];
    const float* uncl  = (const float*)d_in[2];
    const int*   p_ih  = (const int*)d_in[3];
    const int*   p_iw  = (const int*)d_in[4];
    float* out = (float*)d_out;

    dim3 grid1(WDIM / 32, HDIM / 32, BATCH);
    peaks_kernel<<<grid1, 256>>>(route, uncl);

    dim3 grid2(NTILES / TPC, BATCH);
    prepare_kernel<<<grid2, 256>>>(route, uncl);

    sort_emit_kernel<<<BATCH, 1024>>>(uncl, scale, p_ih, p_iw, out);
}

// round 16
// speedup vs baseline: 1.5581x; 1.1793x over previous
#include <cuda_runtime.h>
#include <cstdint>

#define BATCH 32
#define HDIM 512
#define WDIM 512
#define NPIX (HDIM * WDIM)
#define KTOP 1000
#define KPRIME 1280
#define NTILES 256          // 16 x 16 tiles of 32x32
#define MAXTILE 256
#define TPC 16              // tiles per prepare-CTA
#define NSEL 2048
#define STAGE_CAP 1536
#define HBINS 512
#define DELTA 2e-4f
#define APITCH 36

// -------- static device scratch (zero-initialized at module load) --------
__device__ unsigned long long g_tile[BATCH][NTILES][MAXTILE];
__device__ int g_tcnt[BATCH][NTILES];
__device__ unsigned int g_hist[BATCH][HBINS];        // re-zeroed by sort_emit
__device__ unsigned long long g_sel[BATCH][NSEL];
__device__ int g_nsel[BATCH];                        // re-zeroed by sort_emit

// -------- XLA:CPU GenerateVF32Exp (Cephes, non-FMA) — bit-exact reference --------
__device__ __forceinline__ float xla_cpu_expf(float x) {
    const float exp_hi = 88.3762626647950f;
    const float exp_lo = -88.3762626647949f;
    const float log2ef = 1.44269504088896341f;
    const float c1 = 0.693359375f;
    const float c2 = -2.12194440e-4f;

    float xc = fminf(fmaxf(x, exp_lo), exp_hi);
    float fx = floorf(__fadd_rn(__fmul_rn(xc, log2ef), 0.5f));
    float tmp = __fmul_rn(c1, fx);
    float z = __fmul_rn(c2, fx);
    float r = __fsub_rn(xc, tmp);
    r = __fsub_rn(r, z);
    z = __fmul_rn(r, r);

    float y = 1.9875691500E-4f;
    y = __fadd_rn(__fmul_rn(y, r), 1.3981999507E-3f);
    y = __fadd_rn(__fmul_rn(y, r), 8.3334519073E-3f);
    y = __fadd_rn(__fmul_rn(y, r), 4.1665795894E-2f);
    y = __fadd_rn(__fmul_rn(y, r), 1.6666665459E-1f);
    y = __fadd_rn(__fmul_rn(y, r), 5.0000001201E-1f);
    y = __fadd_rn(__fmul_rn(y, z), r);
    y = __fadd_rn(y, 1.0f);

    int emm0 = (((int)fx) + 0x7f) << 23;
    return __fmul_rn(y, __int_as_float(emm0));
}

__device__ __forceinline__ float xla_sigmoidf(float x) {
    float e = xla_cpu_expf(-x);
    return __fdiv_rn(1.0f, __fadd_rn(1.0f, e));
}

__device__ __forceinline__ float score_fn(float r, float u) {
    float s  = xla_sigmoidf(r);
    float p  = __fmul_rn(s, s);
    float su = xla_sigmoidf(u);
    float m  = __fsub_rn(1.0f, __fmul_rn(0.35f, su));
    return __fmul_rn(p, m);
}

// cheap approximate score via single reciprocal:
// s^2 * (1 - 0.35*su) == (0.65 + e_u) / ((1+e_r)^2 (1+e_u));  |err| <= ~1e-5 << DELTA
__device__ __forceinline__ float approx_score(float r, float u) {
    float er = __expf(-r);
    float eu = __expf(-u);
    float d1 = 1.0f + er;
    float den = d1 * d1 * (1.0f + eu);
    return __fdividef(0.65f + eu, den);
}

// 9-bit monotone bin: exponents 119..126 (scores in [2^-8,1)), 6 mantissa bits.
__device__ __forceinline__ unsigned binkey_of(unsigned sb) {
    return (sb < 0x3B800000u) ? 0u : (((sb >> 17) & 0x3FFu) - 448u);
}

// warp-wide inclusive suffix sum (lane l gets sum over lanes >= l)
__device__ __forceinline__ unsigned warp_suffix(unsigned x, int lane) {
    #pragma unroll
    for (int off = 1; off < 32; off <<= 1) {
        unsigned v = __shfl_down_sync(0xFFFFFFFFu, x, off);
        if (lane + off < 32) x += v;
    }
    return x;
}

__device__ __forceinline__ unsigned long long ullmin2(unsigned long long a, unsigned long long b) {
    return a < b ? a : b;
}
__device__ __forceinline__ unsigned long long ullmax2(unsigned long long a, unsigned long long b) {
    return a > b ? a : b;
}

// -------- kernel 1: approx score + separable-max margin NMS (32x32 tiles, float4) --------
__global__ __launch_bounds__(256) void peaks_kernel(const float* __restrict__ route,
                                                    const float* __restrict__ unc) {
    __shared__ float ap[34 * APITCH];          // APITCH=36, divisible by 4
    __shared__ unsigned int sh_hist[HBINS];
    __shared__ unsigned long long sbuf[MAXTILE];
    __shared__ int scnt;

    int b = blockIdx.z;
    int tileId = blockIdx.y * 16 + blockIdx.x;
    int tx0 = blockIdx.x * 32;
    int ty0 = blockIdx.y * 32;
    const float* rp = route + (size_t)b * NPIX;
    const float* up = unc + (size_t)b * NPIX;
    int tid = threadIdx.x;

    if (tid == 0) scnt = 0;
    sh_hist[tid] = 0u;
    if (tid < HBINS - 256) sh_hist[tid + 256] = 0u;

    bool interior = (blockIdx.x > 0) && (blockIdx.x < 15) &&
                    (blockIdx.y > 0) && (blockIdx.y < 15);

    // stage approx scores: 34 rows x 10 aligned float4 items covering gx in [tx0-4, tx0+36)
    for (int it = tid; it < 340; it += 256) {
        int r = it / 10;                 // 0..33 (const-div -> mul/shift)
        int i = it - r * 10;             // 0..9
        int gy = ty0 - 1 + r;
        int gx4 = tx0 - 4 + (i << 2);
        int s0 = (i << 2) - 3;           // smem col of element 0 (s = gx - tx0 + 1)
        float a0, a1, a2, a3;
        if (interior) {
            int vi = ((gy << 9) | gx4) >> 2;
            float4 rv = ((const float4*)rp)[vi];
            float4 uv = ((const float4*)up)[vi];
            a0 = approx_score(rv.x, uv.x);
            a1 = approx_score(rv.y, uv.y);
            a2 = approx_score(rv.z, uv.z);
            a3 = approx_score(rv.w, uv.w);
        } else {
            bool rowok = ((unsigned)gy < (unsigned)HDIM);
            float av[4];
            #pragma unroll
            for (int e = 0; e < 4; e++) {
                int gx = gx4 + e;
                float a = -1e30f;
                if (rowok && (unsigned)gx < (unsigned)WDIM) {
                    int idx = (gy << 9) | gx;
                    a = approx_score(rp[idx], up[idx]);
                }
                av[e] = a;
            }
            a0 = av[0]; a1 = av[1]; a2 = av[2]; a3 = av[3];
        }
        int base = r * APITCH + s0;
        if ((unsigned)s0 < (unsigned)APITCH)       ap[base]     = a0;
        if ((unsigned)(s0 + 1) < (unsigned)APITCH) ap[base + 1] = a1;
        if ((unsigned)(s0 + 2) < (unsigned)APITCH) ap[base + 2] = a2;
        if ((unsigned)(s0 + 3) < (unsigned)APITCH) ap[base + 3] = a3;
    }
    __syncthreads();

    // NMS: each thread handles a 1x4 strip; rows via float4 smem loads.
    {
        int row = tid >> 3;               // 0..31
        int c0 = (tid & 7) << 2;          // 0,4,...,28
        int q = ((row + 1) * APITCH + c0) >> 2;   // float4 index; APITCH/4 = 9
        const float4* ap4 = (const float4*)ap;

        float4 t0 = ap4[q - 9], t1 = ap4[q - 8];
        float4 m0 = ap4[q],     m1 = ap4[q + 1];
        float4 b0 = ap4[q + 9], b1 = ap4[q + 10];

        float vm2[6], h3[6], mid[5];
        vm2[0] = fmaxf(t0.x, b0.x); vm2[1] = fmaxf(t0.y, b0.y);
        vm2[2] = fmaxf(t0.z, b0.z); vm2[3] = fmaxf(t0.w, b0.w);
        vm2[4] = fmaxf(t1.x, b1.x); vm2[5] = fmaxf(t1.y, b1.y);
        h3[0] = fmaxf(vm2[0], m0.x); h3[1] = fmaxf(vm2[1], m0.y);
        h3[2] = fmaxf(vm2[2], m0.z); h3[3] = fmaxf(vm2[3], m0.w);
        h3[4] = fmaxf(vm2[4], m1.x); h3[5] = fmaxf(vm2[5], m1.y);
        mid[0] = m0.y; mid[1] = m0.z; mid[2] = m0.w; mid[3] = m1.x;

        #pragma unroll
        for (int jj = 0; jj < 4; jj++) {
            float a = mid[jj];
            float nmax = fmaxf(fmaxf(h3[jj], h3[jj + 2]), vm2[jj + 1]);
            float d = a - nmax;
            if (d >= -DELTA) {                 // not a definite loss
                bool amb = (d <= DELTA);
                unsigned idx = (unsigned)(((ty0 + row) << 9) | (tx0 + c0 + jj));
                unsigned sb = __float_as_uint(a);
                unsigned lo = idx | (amb ? 0x80000000u : 0u);
                unsigned long long key =
                    ((unsigned long long)sb << 32) | (unsigned long long)lo;
                int pp = atomicAdd(&scnt, 1);
                if (pp < MAXTILE) {
                    sbuf[pp] = key;
                    atomicAdd(&sh_hist[binkey_of(sb)], 1u);
                }
            }
        }
    }
    __syncthreads();

    int nc = scnt; if (nc > MAXTILE) nc = MAXTILE;
    if (tid == 0) g_tcnt[b][tileId] = nc;
    if (tid < nc) g_tile[b][tileId][tid] = sbuf[tid];
    {
        unsigned c = sh_hist[tid];
        if (c) atomicAdd(&g_hist[b][tid], c);
        if (tid < HBINS - 256) {
            unsigned c2 = sh_hist[tid + 256];
            if (c2) atomicAdd(&g_hist[b][tid + 256], c2);
        }
    }
}

// -------- kernel 2: per-batch threshold + compact + exact rescore (512 CTAs) --------
__global__ __launch_bounds__(256) void prepare_kernel(const float* __restrict__ route,
                                                      const float* __restrict__ unc) {
    __shared__ unsigned long long sbuf[STAGE_CAP];
    __shared__ unsigned int wtot[8];
    __shared__ unsigned int wsuf[32];
    __shared__ int sB;
    __shared__ int s_stage;

    int b = blockIdx.y;
    int t0 = blockIdx.x * TPC;
    int tid = threadIdx.x;
    int wid = tid >> 5, lane = tid & 31;

    if (tid == 0) { sB = 0; s_stage = 0; }
    __syncthreads();

    // ---- threshold scan: thread owns bins [2*tid, 2*tid+2) of g_hist[b] ----
    unsigned hb0 = g_hist[b][tid * 2];
    unsigned hb1 = g_hist[b][tid * 2 + 1];
    unsigned tsum = hb0 + hb1;
    unsigned x = warp_suffix(tsum, lane);
    if (lane == 0) wtot[wid] = x;
    __syncthreads();
    if (wid == 0) {
        unsigned w = (lane < 8) ? wtot[lane] : 0u;
        unsigned y = warp_suffix(w, lane);
        wsuf[lane] = y;
    }
    __syncthreads();
    {
        unsigned later = (wid + 1 < 8) ? wsuf[wid + 1] : 0u;
        unsigned inc = x + later;                 // count over bins >= 2*tid
        unsigned above = inc - tsum;              // count over bins >= 2*tid+2
        if (above < (unsigned)KPRIME && inc >= (unsigned)KPRIME) {
            if (above + hb1 >= (unsigned)KPRIME) sB = tid * 2 + 1;
            else sB = tid * 2;
        }
    }
    __syncthreads();
    int B = sB;

    // ---- compact this CTA's TPC tiles: keys with bin >= B -> smem stage ----
    for (int t = t0 + wid; t < t0 + TPC; t += 8) {
        int n = g_tcnt[b][t];
        int nr = (n + 31) & ~31;
        for (int i = lane; i < nr; i += 32) {
            bool valid = (i < n);
            unsigned long long key = valid ? g_tile[b][t][i] : 0ull;
            bool take = valid &&
                        (binkey_of((unsigned)(key >> 32)) >= (unsigned)B);
            unsigned m = __ballot_sync(0xFFFFFFFFu, take);
            if (take) {
                int leader = __ffs(m) - 1;
                int rank = __popc(m & ((1u << lane) - 1u));
                int base = 0;
                if (lane == leader) base = atomicAdd(&s_stage, __popc(m));
                base = __shfl_sync(m, base, leader);
                int p = base + rank;
                if (p < STAGE_CAP) sbuf[p] = key;
            }
        }
    }
    __syncthreads();

    // ---- exact rescore of staged keys; survivors -> g_sel[b] ----
    const float* rp = route + (size_t)b * NPIX;
    const float* up = unc + (size_t)b * NPIX;
    const int DY[8] = {-1,-1,-1, 0, 0, 1, 1, 1};
    const int DX[8] = {-1, 0, 1,-1, 1,-1, 0, 1};

    int m = s_stage; if (m > STAGE_CAP) m = STAGE_CAP;
    int mr = (m + 255) & ~255;
    for (int i = tid; i < mr; i += 256) {
        bool valid = (i < m);
        unsigned long long nk = 0ull;
        bool ok = false;
        if (valid) {
            unsigned lo = (unsigned)sbuf[i];
            unsigned idx = lo & 0x3FFFFu;
            bool amb = (lo >> 31) != 0u;
            float v = score_fn(rp[idx], up[idx]);
            ok = true;
            if (amb) {
                int y = (int)(idx >> 9), x2i = (int)(idx & 511);
                #pragma unroll
                for (int j = 0; j < 8; j++) {
                    int nx = x2i + DX[j], ny = y + DY[j];
                    if (nx >= 0 && nx < WDIM && ny >= 0 && ny < HDIM) {
                        int nidx = (ny << 9) | nx;
                        float vn = score_fn(rp[nidx], up[nidx]);
                        if (!(v >= vn)) { ok = false; break; }
                    }
                }
            }
            if (ok) {
                nk = ((unsigned long long)__float_as_uint(v) << 32) |
                     (unsigned long long)(~idx);
            }
        }
        unsigned bm = __ballot_sync(0xFFFFFFFFu, ok);
        if (ok) {
            int leader = __ffs(bm) - 1;
            int rank = __popc(bm & ((1u << lane) - 1u));
            int base = 0;
            if (lane == leader) base = atomicAdd(&g_nsel[b], __popc(bm));
            base = __shfl_sync(bm, base, leader);
            int p = base + rank;
            if (p < NSEL) g_sel[b][p] = nk;
        }
    }
}

// -------- kernel 3: sort exact keys + emit (32 CTAs) --------
__global__ __launch_bounds__(1024) void sort_emit_kernel(const float* __restrict__ unc,
                                                         const float* __restrict__ scale,
                                                         const int* __restrict__ p_ih,
                                                         const int* __restrict__ p_iw,
                                                         float* __restrict__ out) {
    __shared__ unsigned long long skeys[NSEL];

    int b = blockIdx.x;
    int tid = threadIdx.x;

    int n = g_nsel[b]; if (n > NSEL) n = NSEL;
    skeys[tid]        = (tid < n)        ? g_sel[b][tid]        : 0ull;
    skeys[tid + 1024] = (tid + 1024 < n) ? g_sel[b][tid + 1024] : 0ull;
    __syncthreads();

    // register/shfl bitonic sort of 2048 (ascending; zeros sort to front)
    {
        unsigned long long v0 = skeys[tid];
        unsigned long long v1 = skeys[tid + 1024];
        const int i0 = tid, i1 = tid + 1024;

        for (int size = 2; size <= 2048; size <<= 1) {
            for (int stride = size >> 1; stride > 0; stride >>= 1) {
                if (stride == 1024) {
                    bool up0 = ((i0 & size) == 0);
                    if ((v0 > v1) == up0) { unsigned long long t = v0; v0 = v1; v1 = t; }
                } else if (stride >= 32) {
                    __syncthreads();
                    skeys[i0] = v0; skeys[i1] = v1;
                    __syncthreads();
                    unsigned long long p0 = skeys[i0 ^ stride];
                    unsigned long long p1 = skeys[i1 ^ stride];
                    bool up0 = ((i0 & size) == 0), le0 = ((i0 & stride) == 0);
                    bool up1 = ((i1 & size) == 0), le1 = ((i1 & stride) == 0);
                    v0 = (le0 == up0) ? ullmin2(v0, p0) : ullmax2(v0, p0);
                    v1 = (le1 == up1) ? ullmin2(v1, p1) : ullmax2(v1, p1);
                } else {
                    unsigned long long p0 = __shfl_xor_sync(0xFFFFFFFFu, v0, stride);
                    unsigned long long p1 = __shfl_xor_sync(0xFFFFFFFFu, v1, stride);
                    bool up0 = ((i0 & size) == 0), le0 = ((i0 & stride) == 0);
                    bool up1 = ((i1 & size) == 0), le1 = ((i1 & stride) == 0);
                    v0 = (le0 == up0) ? ullmin2(v0, p0) : ullmax2(v0, p0);
                    v1 = (le1 == up1) ? ullmin2(v1, p1) : ullmax2(v1, p1);
                }
            }
        }
        __syncthreads();
        skeys[i0] = v0; skeys[i1] = v1;
        __syncthreads();
    }

    int k = n; if (k > KTOP) k = KTOP;
    const float* up = unc + (size_t)b * NPIX;

    if (tid < KTOP) {
        float iw = (float)p_iw[0];
        float ih = (float)p_ih[0];
        float bcol = 0.f, x1 = 0.f, y1 = 0.f, x2 = 0.f, y2 = 0.f, scv = 0.f, vv = 0.f;
        if (tid < k) {
            unsigned long long key = skeys[2047 - tid];
            float v = __uint_as_float((unsigned)(key >> 32));
            unsigned idx = (~((unsigned)key)) & 0x3FFFFu;
            int y = (int)(idx >> 9);
            int x = (int)(idx & 511);
            float cx = __fmul_rn(__fadd_rn((float)x, 0.5f), 4.0f);
            float cy = __fmul_rn(__fadd_rn((float)y, 0.5f), 4.0f);
            float sc = scale[(size_t)b * NPIX + idx];
            float un = xla_sigmoidf(up[idx]);
            float side = __fadd_rn(32.0f, __fmul_rn(xla_sigmoidf(sc), 480.0f));
            side = __fmul_rn(side, __fadd_rn(1.0f, __fmul_rn(0.25f, un)));
            float half = __fmul_rn(side, 0.5f);
            x1 = fminf(fmaxf(__fsub_rn(cx, half), 0.0f), __fsub_rn(iw, 1.0f));
            y1 = fminf(fmaxf(__fsub_rn(cy, half), 0.0f), __fsub_rn(ih, 1.0f));
            x2 = fminf(fmaxf(__fadd_rn(cx, half), 1.0f), iw);
            y2 = fminf(fmaxf(__fadd_rn(cy, half), 1.0f), ih);
            bcol = (float)b;
            scv = v;
            vv = 1.0f;
        }
        int t = b * KTOP + tid;
        float* roi = out + (size_t)t * 5;
        roi[0] = bcol; roi[1] = x1; roi[2] = y1; roi[3] = x2; roi[4] = y2;
        out[(size_t)BATCH * KTOP * 5 + t] = scv;
        out[(size_t)BATCH * KTOP * 6 + t] = vv;
    }

    // cleanup for next graph replay (deterministic state)
    if (tid < HBINS) g_hist[b][tid] = 0u;
    if (tid == 0) g_nsel[b] = 0;
}

extern "C" void kernel_launch(void* const* d_in, const int* in_sizes, int n_in,
                              void* d_out, int out_size) {
    const float* route = (const float*)d_in[0];
    const float* scale = (const float*)d_in[1];
    const float* uncl  = (const float*)d_in[2];
    const int*   p_ih  = (const int*)d_in[3];
    const int*   p_iw  = (const int*)d_in[4];
    float* out = (float*)d_out;

    dim3 grid1(WDIM / 32, HDIM / 32, BATCH);
    peaks_kernel<<<grid1, 256>>>(route, uncl);

    dim3 grid2(NTILES / TPC, BATCH);
    prepare_kernel<<<grid2, 256>>>(route, uncl);

    sort_emit_kernel<<<BATCH, 1024>>>(uncl, scale, p_ih, p_iw, out);
}